// round 13
// baseline (speedup 1.0000x reference)
#include <cuda_runtime.h>

// CTRNN forward on GB300 — round 9: one CTA per SM, no SMSP stacking.
// 128 CTAs x 128 threads; each CTA owns TWO batches so its 4 warps cover all
// 4 SMSPs (wid%4). Phase 1 (prologue): CTA computes xp = a(x@W_in^T+b) for its
// two batches into global scratch. Phase 2: proven k-packed 2-warp scan, run
// as two independent 64-thread groups, one CTA __syncthreads per step.
// Inputs (metadata order): x[B,T,D] f32, seq_lengths[B] i32 (forward no-op),
// W_in[H,D] f32, b_in[H] f32, W_hh[H,H] f32, b_hh[H] f32.
// Output: outputs[B,T,H] then h_last[B,H], f32, concatenated flat.

#define BB 256
#define TT 2048
#define DD 32
#define HH 64
#define PF 8                 // xp ring depth (steps); TT % PF == 0

typedef unsigned long long u64;

// Scratch for xp, [B][T][H], padded by PF rows so ring refills are unconditional.
__device__ __align__(16) float g_xp[(size_t)BB * TT * HH + PF * HH];

__device__ __forceinline__ u64 pack2(float lo, float hi) {
    u64 r; asm("mov.b64 %0, {%1, %2};" : "=l"(r) : "f"(lo), "f"(hi)); return r;
}
__device__ __forceinline__ float2 unpack2(u64 v) {
    float2 f; asm("mov.b64 {%0, %1}, %2;" : "=f"(f.x), "=f"(f.y) : "l"(v)); return f;
}
// Packed fp32x2 FMA (Blackwell FFMA2): d = a*b + d.
__device__ __forceinline__ void ffma2(u64& d, u64 a, u64 b) {
    asm("fma.rn.f32x2 %0, %1, %2, %0;" : "+l"(d) : "l"(a), "l"(b));
}
__device__ __forceinline__ u64 add2(u64 a, u64 b) {
    u64 r; asm("add.rn.f32x2 %0, %1, %2;" : "=l"(r) : "l"(a), "l"(b)); return r;
}

#define ALPHA_F ((float)(16.67 / 40.0))
#define OMA_F   ((float)(1.0 - 16.67 / 40.0))

__global__ void __launch_bounds__(128) ctrnn_kernel(
    const float* __restrict__ x,
    const float* __restrict__ W_in,
    const float* __restrict__ b_in,
    const float* __restrict__ W_hh,
    const float* __restrict__ b_hh,
    float* __restrict__ out)
{
    const int tid = threadIdx.x;
    const int b0  = 2 * blockIdx.x;                 // this CTA's first batch

    __shared__ __align__(16) float hbuf[2][2][HH];  // [group][buf][HH]

    // ================= Phase 1: xp for batches b0, b0+1 =====================
    // Rows are contiguous across the two batches: 2*TT rows of x / xp.
    {
        const int warp = tid >> 5;
        const int l    = tid & 31;
        const int j0   = 2 * l, j1 = 2 * l + 1;

        // K-pair weights: w0[k]=(a*W_in[j0][2k], a*W_in[j0][2k+1]); same for j1.
        u64 w0[DD / 2], w1[DD / 2];
        #pragma unroll
        for (int k4 = 0; k4 < DD / 4; k4++) {
            float4 a = ((const float4*)(W_in + j0 * DD))[k4];
            float4 c = ((const float4*)(W_in + j1 * DD))[k4];
            w0[2 * k4]     = pack2(ALPHA_F * a.x, ALPHA_F * a.y);
            w0[2 * k4 + 1] = pack2(ALPHA_F * a.z, ALPHA_F * a.w);
            w1[2 * k4]     = pack2(ALPHA_F * c.x, ALPHA_F * c.y);
            w1[2 * k4 + 1] = pack2(ALPHA_F * c.z, ALPHA_F * c.w);
        }
        const float bias0 = ALPHA_F * (b_in[j0] + b_hh[j0]);
        const float bias1 = ALPHA_F * (b_in[j1] + b_hh[j1]);

        const float* xb = x + (size_t)b0 * TT * DD;
        u64* xpw = (u64*)(g_xp + (size_t)b0 * TT * HH);

        // Warp w covers rows r == w (mod 4); two rows in flight for MLP.
        for (int r = warp; r < 2 * TT; r += 8) {
            const int r2 = r + 4;
            const ulonglong2* xa = (const ulonglong2*)(xb + (size_t)r  * DD);
            const ulonglong2* xc = (const ulonglong2*)(xb + (size_t)r2 * DD);
            u64 a0 = 0, a1 = 0, b0v = 0, b1v = 0;
            u64 c0 = 0, c1 = 0, d0v = 0, d1v = 0;
            #pragma unroll
            for (int i = 0; i < DD / 4; i++) {       // 8+8 broadcast LDG.128
                ulonglong2 q = xa[i];
                ffma2(a0,  q.x, w0[2 * i]);
                ffma2(b0v, q.x, w1[2 * i]);
                ffma2(a1,  q.y, w0[2 * i + 1]);
                ffma2(b1v, q.y, w1[2 * i + 1]);
            }
            #pragma unroll
            for (int i = 0; i < DD / 4; i++) {
                ulonglong2 q = xc[i];
                ffma2(c0,  q.x, w0[2 * i]);
                ffma2(d0v, q.x, w1[2 * i]);
                ffma2(c1,  q.y, w0[2 * i + 1]);
                ffma2(d1v, q.y, w1[2 * i + 1]);
            }
            float2 s0 = unpack2(add2(a0, a1)), s1 = unpack2(add2(b0v, b1v));
            xpw[(size_t)r * 32 + l]  = pack2(s0.x + s0.y + bias0,
                                             s1.x + s1.y + bias1);
            float2 s2 = unpack2(add2(c0, c1)), s3 = unpack2(add2(d0v, d1v));
            xpw[(size_t)r2 * 32 + l] = pack2(s2.x + s2.y + bias0,
                                             s3.x + s3.y + bias1);
        }
    }

    // ================= Phase 2: two independent scans =======================
    const int g = tid >> 6;          // group 0/1 -> batch b0+g
    const int j = tid & 63;          // output index within group
    const int bb = b0 + g;

    // K-pair recurrent weights for output j: 32 u64 = 64 regs.
    u64 wk[HH / 2];
    #pragma unroll
    for (int k4 = 0; k4 < HH / 4; k4++) {
        float4 v = ((const float4*)(W_hh + j * HH))[k4];
        wk[2 * k4]     = pack2(ALPHA_F * v.x, ALPHA_F * v.y);
        wk[2 * k4 + 1] = pack2(ALPHA_F * v.z, ALPHA_F * v.w);
    }

    hbuf[g][0][j] = 0.0f;
    float hold = 0.0f;
    __syncthreads();   // also publishes phase-1 xp (global, same CTA)

    // xp prefetch ring: one float per lane per step (bias already folded).
    const float* xpb = g_xp + (size_t)bb * TT * HH;
    float xr[PF];
    #pragma unroll
    for (int p = 0; p < PF; p++) xr[p] = xpb[p * HH + j];

    float* outb = out + (size_t)bb * TT * HH;

    for (int t0 = 0; t0 < TT; t0 += PF) {
        #pragma unroll
        for (int p = 0; p < PF; p++) {
            const int t   = t0 + p;
            const int cur = t & 1;

            // acc = xp(t) + OMA*h_j + h(t-1).(a*W_hh[j,:]) : 16 LDS.128, 32 ffma2
            u64 a0 = pack2(xr[p], 0.0f), a1 = 0, a2 = 0, a3 = 0;
            ffma2(a1, pack2(hold, 0.0f), pack2(OMA_F, 0.0f));
            const ulonglong2* hv = (const ulonglong2*)hbuf[g][cur];  // broadcast
            #pragma unroll
            for (int i = 0; i < HH / 4; i++) {
                ulonglong2 hq = hv[i];
                if (i & 1) { ffma2(a2, hq.x, wk[2 * i]); ffma2(a3, hq.y, wk[2 * i + 1]); }
                else       { ffma2(a0, hq.x, wk[2 * i]); ffma2(a1, hq.y, wk[2 * i + 1]); }
            }
            float2 sf = unpack2(add2(add2(a0, a1), add2(a2, a3)));
            float hnew = fmaxf(sf.x + sf.y, 0.0f);

            hbuf[g][cur ^ 1][j] = hnew;            // STS.32 (serial chain)
            outb[(size_t)t * HH + j] = hnew;       // coalesced STG.32
            hold = hnew;

            // Refill ring with xp(t+PF): unconditional (g_xp padded; overreads
            // into the next batch's region are never consumed).
            xr[p] = xpb[(size_t)(t + PF) * HH + j];

            __syncthreads();   // one 4-warp CTA barrier per step
        }
    }

    out[(size_t)BB * TT * HH + (size_t)bb * HH + j] = hold;
}

extern "C" void kernel_launch(void* const* d_in, const int* in_sizes, int n_in,
                              void* d_out, int out_size) {
    (void)in_sizes; (void)n_in; (void)out_size;
    const float* x    = (const float*)d_in[0];
    // d_in[1] = seq_lengths: forward no-op (mask only gates gradients)
    const float* W_in = (const float*)d_in[2];
    const float* b_in = (const float*)d_in[3];
    const float* W_hh = (const float*)d_in[4];
    const float* b_hh = (const float*)d_in[5];

    ctrnn_kernel<<<BB / 2, 128>>>(x, W_in, b_in, W_hh, b_hh, (float*)d_out);
}

// round 14
// speedup vs baseline: 2.0016x; 2.0016x over previous
#include <cuda_runtime.h>

// CTRNN forward on GB300 — round 10.
// Scan = round-8 verbatim (proven 309us: 2 warps/CTA, one output/lane,
// k-packed f32x2, one 2-warp __syncthreads per step — nothing else coupled).
// Pass 1 rebuilt: smem-staged, double-buffered, coalesced; 1024 CTAs.
// Inputs (metadata order): x[B,T,D] f32, seq_lengths[B] i32 (forward no-op),
// W_in[H,D] f32, b_in[H] f32, W_hh[H,H] f32, b_hh[H] f32.
// Output: outputs[B,T,H] then h_last[B,H], f32, concatenated flat.

#define BB 256
#define TT 2048
#define DD 32
#define HH 64
#define PF 8                 // xp ring depth (steps); TT % PF == 0

typedef unsigned long long u64;

// Scratch for xp, [B][T][H], padded by PF rows so ring refills are unconditional.
__device__ __align__(16) float g_xp[(size_t)BB * TT * HH + PF * HH];

__device__ __forceinline__ u64 pack2(float lo, float hi) {
    u64 r; asm("mov.b64 %0, {%1, %2};" : "=l"(r) : "f"(lo), "f"(hi)); return r;
}
__device__ __forceinline__ float2 unpack2(u64 v) {
    float2 f; asm("mov.b64 {%0, %1}, %2;" : "=f"(f.x), "=f"(f.y) : "l"(v)); return f;
}
// Packed fp32x2 FMA (Blackwell FFMA2): d = a*b + d.
__device__ __forceinline__ void ffma2(u64& d, u64 a, u64 b) {
    asm("fma.rn.f32x2 %0, %1, %2, %0;" : "+l"(d) : "l"(a), "l"(b));
}
__device__ __forceinline__ u64 add2(u64 a, u64 b) {
    u64 r; asm("add.rn.f32x2 %0, %1, %2;" : "=l"(r) : "l"(a), "l"(b)); return r;
}

#define ALPHA_F ((float)(16.67 / 40.0))
#define OMA_F   ((float)(1.0 - 16.67 / 40.0))

// ---------------- Pass 1: xp[r,j] = ALPHA*(x[r,:] . W_in[j,:] + b_in[j] + b_hh[j])
// Tiled: 64 rows (8KB) staged into smem with coalesced LDG.128, double-buffered.
// 8 warps/CTA, each computes 8 rows from broadcast LDS. 1024 CTAs x 8 tiles.
#define XPT_ROWS    64
#define XPT_CTAS    1024
#define XPT_THREADS 256
#define XPT_NTILES  ((BB * TT) / XPT_ROWS)            // 8192
#define XPT_TPC     (XPT_NTILES / XPT_CTAS)           // 8 tiles per CTA

__global__ void __launch_bounds__(XPT_THREADS) xproj_kernel(
    const float* __restrict__ x,
    const float* __restrict__ W_in,
    const float* __restrict__ b_in,
    const float* __restrict__ b_hh)
{
    __shared__ __align__(16) float xs[2][XPT_ROWS][DD];   // 2 x 8KB

    const int tid  = threadIdx.x;
    const int warp = tid >> 5;
    const int l    = tid & 31;
    const int j0   = 2 * l, j1 = 2 * l + 1;

    // K-pair weights: w0[k]=(a*W_in[j0][2k], a*W_in[j0][2k+1]); same for j1.
    u64 w0[DD / 2], w1[DD / 2];
    #pragma unroll
    for (int k4 = 0; k4 < DD / 4; k4++) {
        float4 a = ((const float4*)(W_in + j0 * DD))[k4];
        float4 c = ((const float4*)(W_in + j1 * DD))[k4];
        w0[2 * k4]     = pack2(ALPHA_F * a.x, ALPHA_F * a.y);
        w0[2 * k4 + 1] = pack2(ALPHA_F * a.z, ALPHA_F * a.w);
        w1[2 * k4]     = pack2(ALPHA_F * c.x, ALPHA_F * c.y);
        w1[2 * k4 + 1] = pack2(ALPHA_F * c.z, ALPHA_F * c.w);
    }
    const float bias0 = ALPHA_F * (b_in[j0] + b_hh[j0]);
    const float bias1 = ALPHA_F * (b_in[j1] + b_hh[j1]);

    const int tile0 = blockIdx.x * XPT_TPC;    // contiguous tile range per CTA
    const float4* xg4 = (const float4*)x;      // tile t = float4s [t*512, t*512+512)
    u64* xpw = (u64*)g_xp;

    // Prologue: stage tile0 into buf 0 (each thread: 2 coalesced float4).
    {
        const size_t base = (size_t)tile0 * (XPT_ROWS * DD / 4);
        ((float4*)xs[0])[tid]               = xg4[base + tid];
        ((float4*)xs[0])[tid + XPT_THREADS] = xg4[base + tid + XPT_THREADS];
    }
    __syncthreads();

    for (int tt = 0; tt < XPT_TPC; tt++) {
        const int buf  = tt & 1;
        const int tile = tile0 + tt;

        // Issue next tile's loads before computing (overlap DRAM latency).
        float4 s0, s1;
        if (tt + 1 < XPT_TPC) {
            const size_t base = (size_t)(tile + 1) * (XPT_ROWS * DD / 4);
            s0 = xg4[base + tid];
            s1 = xg4[base + tid + XPT_THREADS];
        }

        // Compute: warp w handles rows w*8 .. w*8+7 of this tile.
        #pragma unroll
        for (int r8 = 0; r8 < 8; r8++) {
            const int row = warp * 8 + r8;
            const ulonglong2* xv = (const ulonglong2*)xs[buf][row];  // broadcast
            u64 a0 = 0, a1 = 0, b0v = 0, b1v = 0;
            #pragma unroll
            for (int i = 0; i < DD / 4; i++) {
                ulonglong2 q = xv[i];
                ffma2(a0,  q.x, w0[2 * i]);
                ffma2(b0v, q.x, w1[2 * i]);
                ffma2(a1,  q.y, w0[2 * i + 1]);
                ffma2(b1v, q.y, w1[2 * i + 1]);
            }
            float2 sA = unpack2(add2(a0, a1));
            float2 sB = unpack2(add2(b0v, b1v));
            xpw[((size_t)tile * XPT_ROWS + row) * 32 + l] =
                pack2(sA.x + sA.y + bias0, sB.x + sB.y + bias1);   // STG.64
        }
        __syncthreads();   // all reads of buf^1 from previous iter complete
        if (tt + 1 < XPT_TPC) {
            ((float4*)xs[buf ^ 1])[tid]               = s0;
            ((float4*)xs[buf ^ 1])[tid + XPT_THREADS] = s1;
        }
        __syncthreads();   // publish next buffer
    }
}

// ---------------- Pass 2: round-8 scan, verbatim. 2 warps, 1 output per lane.
__global__ void __launch_bounds__(HH) ctrnn_scan_kernel(
    const float* __restrict__ W_hh,
    float* __restrict__ out)
{
    const int b = blockIdx.x;
    const int j = threadIdx.x;     // output index 0..63

    __shared__ __align__(16) float hbuf[2][HH];  // plain h, double-buffered

    // K-pair weights for output j: wk[k] = (a*W[j][2k], a*W[j][2k+1]); 32 u64.
    u64 wk[HH / 2];
    #pragma unroll
    for (int k4 = 0; k4 < HH / 4; k4++) {
        float4 v = ((const float4*)(W_hh + j * HH))[k4];
        wk[2 * k4]     = pack2(ALPHA_F * v.x, ALPHA_F * v.y);
        wk[2 * k4 + 1] = pack2(ALPHA_F * v.z, ALPHA_F * v.w);
    }

    // xp prefetch ring: one float per lane per step (bias already folded in).
    const float* xpb = g_xp + (size_t)b * TT * HH;
    float xr[PF];
    #pragma unroll
    for (int p = 0; p < PF; p++) xr[p] = xpb[p * HH + j];

    hbuf[0][j] = 0.0f;
    float hold = 0.0f;
    __syncthreads();

    float* outb = out + (size_t)b * TT * HH;

    for (int t0 = 0; t0 < TT; t0 += PF) {
        #pragma unroll
        for (int p = 0; p < PF; p++) {
            const int t   = t0 + p;
            const int cur = t & 1;
            const int nxt = cur ^ 1;

            // acc = xp(t) + h(t-1) . (ALPHA*W_hh[j,:]), k-packed:
            // 16 LDS.128 (broadcast), 32 ffma2.
            u64 a0 = pack2(xr[p], 0.0f), a1 = 0, a2 = 0, a3 = 0;
            const ulonglong2* hv = (const ulonglong2*)hbuf[cur];  // broadcast
            #pragma unroll
            for (int i = 0; i < HH / 4; i++) {
                ulonglong2 hq = hv[i];
                if (i & 1) { ffma2(a2, hq.x, wk[2 * i]); ffma2(a3, hq.y, wk[2 * i + 1]); }
                else       { ffma2(a0, hq.x, wk[2 * i]); ffma2(a1, hq.y, wk[2 * i + 1]); }
            }
            float2 sf = unpack2(add2(add2(a0, a1), add2(a2, a3)));
            float hnew = fmaxf(fmaf(hold, OMA_F, sf.x + sf.y), 0.0f);

            outb[(size_t)t * HH + j] = hnew;   // coalesced STG.32
            hbuf[nxt][j] = hnew;               // STS.32

            // Refill ring slot with xp(t+PF). Unconditional: g_xp padded by PF
            // rows; values loaded past TT are never consumed.
            xr[p] = xpb[(size_t)(t + PF) * HH + j];

            hold = hnew;
            __syncthreads();                   // one 2-warp barrier per step
        }
    }

    out[(size_t)BB * TT * HH + (size_t)b * HH + j] = hold;
}

extern "C" void kernel_launch(void* const* d_in, const int* in_sizes, int n_in,
                              void* d_out, int out_size) {
    (void)in_sizes; (void)n_in; (void)out_size;
    const float* x    = (const float*)d_in[0];
    // d_in[1] = seq_lengths: forward no-op (mask only gates gradients)
    const float* W_in = (const float*)d_in[2];
    const float* b_in = (const float*)d_in[3];
    const float* W_hh = (const float*)d_in[4];
    const float* b_hh = (const float*)d_in[5];
    float* out = (float*)d_out;

    xproj_kernel<<<XPT_CTAS, XPT_THREADS>>>(x, W_in, b_in, b_hh);
    ctrnn_scan_kernel<<<BB, HH>>>(W_hh, out);
}